// round 1
// baseline (speedup 1.0000x reference)
#include <cuda_runtime.h>
#include <cuda_bf16.h>
#include <math.h>

// Problem constants (fixed by the reference):
//   Q, K, V: (16, 2048, 256) fp32 ; padding_mask: (16, 2048) int32 ; out: (16, 2048, 256) fp32
#define BATCH    16
#define SEQ      2048
#define DIM      256
#define BR       64     // q rows per CTA
#define BC       64     // k cols per tile
#define QSTR     260    // padded smem row stride (floats) for Q
#define KSTR     260    // padded smem row stride (floats) for K
#define VSTR     256
#define PSTR     64
#define NTHREADS 256

// dynamic smem layout (floats):
//   Qs[BR*QSTR] | Ks[BC*KSTR] | Vs[BC*VSTR] | Ps[BR*PSTR] | pads[BC] (as ints)
#define SMEM_FLOATS (BR*QSTR + BC*KSTR + BC*VSTR + BR*PSTR)
#define SMEM_BYTES  (SMEM_FLOATS * 4 + BC * 4)

__device__ __forceinline__ float redmax16(float v) {
#pragma unroll
    for (int m = 8; m >= 1; m >>= 1)
        v = fmaxf(v, __shfl_xor_sync(0xffffffffu, v, m));
    return v;
}

__device__ __forceinline__ float redsum16(float v) {
#pragma unroll
    for (int m = 8; m >= 1; m >>= 1)
        v += __shfl_xor_sync(0xffffffffu, v, m);
    return v;
}

__global__ __launch_bounds__(NTHREADS, 1)
void attn_fwd_fp32(const float* __restrict__ Qg, const float* __restrict__ Kg,
                   const float* __restrict__ Vg, const int* __restrict__ pad,
                   float* __restrict__ Og) {
    extern __shared__ float sm[];
    float* Qs = sm;                         // BR x QSTR
    float* Ks = Qs + BR * QSTR;             // BC x KSTR
    float* Vs = Ks + BC * KSTR;             // BC x VSTR
    float* Ps = Vs + BC * VSTR;             // BR x PSTR
    int*   pads = (int*)(Ps + BR * PSTR);   // BC

    const int qt  = blockIdx.x;             // q-tile index (0..31)
    const int b   = blockIdx.y;             // batch
    const int tid = threadIdx.x;
    const int tx  = tid & 15;               // 0..15: score-col group / out-col group
    const int ty  = tid >> 4;               // 0..15: q-row group

    // ---- load Q tile (64 x 256) into padded smem ----
    {
        const float4* Q4 = (const float4*)(Qg + ((size_t)b * SEQ + (size_t)qt * BR) * DIM);
#pragma unroll
        for (int t = tid; t < BR * (DIM / 4); t += NTHREADS) {
            int row = t >> 6, c4 = t & 63;
            float4 v = Q4[row * (DIM / 4) + c4];
            *(float4*)&Qs[row * QSTR + c4 * 4] = v;
        }
    }

    // per-thread state: 4 q-rows (ty*4+i), 16 out cols (tx*16 + c)
    float o[4][16];
#pragma unroll
    for (int i = 0; i < 4; i++)
#pragma unroll
        for (int c = 0; c < 16; c++) o[i][c] = 0.f;
    float mrow[4], lrow[4];
#pragma unroll
    for (int i = 0; i < 4; i++) { mrow[i] = -INFINITY; lrow[i] = 0.f; }

    const float scale = 0.0625f;  // 1/sqrt(256)

    for (int j0 = 0; j0 <= qt; ++j0) {
        __syncthreads();  // previous iter's smem reads (K/V/P) done, Q load done (iter 0)

        // ---- load K/V tile (64 x 256 each) + pad slice ----
        {
            const size_t baseK = ((size_t)b * SEQ + (size_t)j0 * BC) * DIM;
            const float4* K4 = (const float4*)(Kg + baseK);
            const float4* V4 = (const float4*)(Vg + baseK);
#pragma unroll
            for (int t = tid; t < BC * (DIM / 4); t += NTHREADS) {
                int row = t >> 6, c4 = t & 63;
                *(float4*)&Ks[row * KSTR + c4 * 4] = K4[row * (DIM / 4) + c4];
                *(float4*)&Vs[row * VSTR + c4 * 4] = V4[row * (DIM / 4) + c4];
            }
            if (tid < BC) pads[tid] = pad[(size_t)b * SEQ + (size_t)j0 * BC + tid];
        }
        __syncthreads();

        // ---- S = Q K^T  (4 rows x 4 strided cols per thread) ----
        float s[4][4];
#pragma unroll
        for (int i = 0; i < 4; i++)
#pragma unroll
            for (int j = 0; j < 4; j++) s[i][j] = 0.f;

#pragma unroll 2
        for (int d = 0; d < DIM; d += 4) {
            float qv[4][4], kv[4][4];
#pragma unroll
            for (int i = 0; i < 4; i++)
                *(float4*)qv[i] = *(const float4*)&Qs[(ty * 4 + i) * QSTR + d];
#pragma unroll
            for (int j = 0; j < 4; j++)
                *(float4*)kv[j] = *(const float4*)&Ks[(tx + 16 * j) * KSTR + d];
#pragma unroll
            for (int i = 0; i < 4; i++)
#pragma unroll
                for (int j = 0; j < 4; j++) {
                    s[i][j] += qv[i][0] * kv[j][0];
                    s[i][j] += qv[i][1] * kv[j][1];
                    s[i][j] += qv[i][2] * kv[j][2];
                    s[i][j] += qv[i][3] * kv[j][3];
                }
        }

        // ---- mask + scale ----
#pragma unroll
        for (int i = 0; i < 4; i++) {
            const int qg = qt * BR + ty * 4 + i;
#pragma unroll
            for (int j = 0; j < 4; j++) {
                const int kcol = tx + 16 * j;
                const int kg = j0 * BC + kcol;
                float sv = s[i][j] * scale;
                if (kg > qg || pads[kcol] == 0) sv = -INFINITY;
                s[i][j] = sv;
            }
        }

        // ---- online softmax update + write P ----
#pragma unroll
        for (int i = 0; i < 4; i++) {
            float rm = fmaxf(fmaxf(s[i][0], s[i][1]), fmaxf(s[i][2], s[i][3]));
            rm = redmax16(rm);
            const float nm = fmaxf(mrow[i], rm);
            const float corr = __expf(mrow[i] - nm);
            float rs = 0.f;
#pragma unroll
            for (int j = 0; j < 4; j++) {
                float p = __expf(s[i][j] - nm);
                s[i][j] = p;
                rs += p;
            }
            rs = redsum16(rs);
            lrow[i] = lrow[i] * corr + rs;
            mrow[i] = nm;
#pragma unroll
            for (int c = 0; c < 16; c++) o[i][c] *= corr;
#pragma unroll
            for (int j = 0; j < 4; j++)
                Ps[(ty * 4 + i) * PSTR + tx + 16 * j] = s[i][j];
        }
        __syncthreads();

        // ---- O += P V  (4 rows x 16 cols per thread, k = 0..63) ----
#pragma unroll 1
        for (int kk = 0; kk < BC; kk += 4) {
            float pr[4][4];
#pragma unroll
            for (int i = 0; i < 4; i++)
                *(float4*)pr[i] = *(const float4*)&Ps[(ty * 4 + i) * PSTR + kk];
#pragma unroll
            for (int s4 = 0; s4 < 4; s4++) {
                float vv[16];
#pragma unroll
                for (int c4 = 0; c4 < 4; c4++)
                    *(float4*)&vv[c4 * 4] =
                        *(const float4*)&Vs[(kk + s4) * VSTR + tx * 16 + c4 * 4];
#pragma unroll
                for (int i = 0; i < 4; i++) {
                    const float p = pr[i][s4];
#pragma unroll
                    for (int c = 0; c < 16; c++) o[i][c] += p * vv[c];
                }
            }
        }
    }

    // ---- epilogue: normalize and store ----
#pragma unroll
    for (int i = 0; i < 4; i++) {
        const float inv = 1.0f / lrow[i];
        float* orow = Og + ((size_t)b * SEQ + (size_t)(qt * BR + ty * 4 + i)) * DIM + tx * 16;
#pragma unroll
        for (int c4 = 0; c4 < 4; c4++) {
            float4 v;
            v.x = o[i][c4 * 4 + 0] * inv;
            v.y = o[i][c4 * 4 + 1] * inv;
            v.z = o[i][c4 * 4 + 2] * inv;
            v.w = o[i][c4 * 4 + 3] * inv;
            *(float4*)&orow[c4 * 4] = v;
        }
    }
}

extern "C" void kernel_launch(void* const* d_in, const int* in_sizes, int n_in,
                              void* d_out, int out_size) {
    const float* Q   = (const float*)d_in[0];
    const float* K   = (const float*)d_in[1];
    const float* V   = (const float*)d_in[2];
    const int*   pad = (const int*)d_in[3];
    float*       O   = (float*)d_out;

    cudaFuncSetAttribute(attn_fwd_fp32,
                         cudaFuncAttributeMaxDynamicSharedMemorySize, SMEM_BYTES);

    dim3 grid(SEQ / BR, BATCH);
    attn_fwd_fp32<<<grid, NTHREADS, SMEM_BYTES>>>(Q, K, V, pad, O);
}